// round 16
// baseline (speedup 1.0000x reference)
#include <cuda_runtime.h>
#include <cuda_bf16.h>
#include <cuda_fp16.h>
#include <cstdint>

#define NN 100000
#define NE 1600000
#define HEADS 8
#define HID 128
#define SCAN_B 1024
#define NB ((NN + SCAN_B - 1) / SCAN_B)   // 98
#define EDGE_CAP 64
#define NSCAT 3125                         // 3125*1024 >= 2*NE
#define GB ((NN + 127) / 128)              // 782 gemm row-blocks

// ------------------------- static scratch (no allocation) -------------------------
static __device__ float  g_xp[(size_t)NN * HID];
static __device__ __half g_xp16[(size_t)NN * HID];    // fp16 mirror for edge gathers
static __device__ float  g_as[2][NN * HEADS];
static __device__ float  g_ad[2][NN * HEADS];
static __device__ float  g_e[2][(size_t)NE * HEADS];  // spill only (deg > EDGE_CAP)
static __device__ int    g_srcs[2][NE];
static __device__ int    g_deg[2][NN];
static __device__ int    g_off[2][NN + 1];
static __device__ int    g_cur[2][NN];
static __device__ int    g_bsum[2][NB];
static __device__ int    g_boff[2][NB + 1];
static __device__ __half g_acc16[2][(size_t)NN * HID]; // fp16 aggregated outputs
static __device__ float  g_ksum[2 * HID];
static __device__ float  g_attn[2];
static __device__ int    g_f64;

// ------------------------- side stream for graph-level parallelism -------------------------
static cudaStream_t g_side = 0;
static cudaEvent_t  g_evf = 0, g_evj = 0;
static bool g_sok = false;
namespace {
struct SInit {
    SInit() {
        g_sok = (cudaStreamCreateWithFlags(&g_side, cudaStreamNonBlocking) == cudaSuccess) &&
                (cudaEventCreateWithFlags(&g_evf, cudaEventDisableTiming) == cudaSuccess) &&
                (cudaEventCreateWithFlags(&g_evj, cudaEventDisableTiming) == cudaSuccess);
    }
};
static SInit s_sinit;
}

// ------------------------- math helpers -------------------------
__device__ __forceinline__ float fexp(float x) {
    float y = x * 1.4426950408889634f;
    float r = rintf(y);
    float f = y - r;
    float p = 1.33336498e-3f;
    p = fmaf(p, f, 9.61011201e-3f);
    p = fmaf(p, f, 5.55040678e-2f);
    p = fmaf(p, f, 2.40226507e-1f);
    p = fmaf(p, f, 6.93147182e-1f);
    p = fmaf(p, f, 1.0f);
    int ir = (int)r;
    ir = ir < -120 ? -120 : (ir > 120 ? 120 : ir);
    return __int_as_float((ir + 127) << 23) * p;
}

__device__ __forceinline__ float ftanh(float x) {
    float cx = fminf(fmaxf(x, -9.f), 9.f);
    float x2 = cx * cx;
    float p = -2.76076847742355e-16f;
    p = fmaf(p, x2, 2.00018790482477e-13f);
    p = fmaf(p, x2, -8.60467152213735e-11f);
    p = fmaf(p, x2, 5.12229709037114e-08f);
    p = fmaf(p, x2, 1.48572235717979e-05f);
    p = fmaf(p, x2, 6.37261928875436e-04f);
    p = fmaf(p, x2, 4.89352455891786e-03f);
    p = p * cx;
    float q = 1.19825839466702e-06f;
    q = fmaf(q, x2, 1.18534705686654e-04f);
    q = fmaf(q, x2, 2.26843463243900e-03f);
    q = fmaf(q, x2, 4.89352518554385e-03f);
    return __fdividef(p, q);
}

// ------------------------- warp-MMA helpers -------------------------
__device__ __forceinline__ uint32_t smem_u32(const void* p) {
    uint32_t a;
    asm("{ .reg .u64 t; cvta.to.shared.u64 t, %1; cvt.u32.u64 %0, t; }" : "=r"(a) : "l"(p));
    return a;
}

__device__ __forceinline__ void mma_bf16(float* c, const uint32_t* a, uint32_t b0, uint32_t b1) {
    asm volatile(
        "mma.sync.aligned.m16n8k16.row.col.f32.bf16.bf16.f32 "
        "{%0,%1,%2,%3}, {%4,%5,%6,%7}, {%8,%9}, {%0,%1,%2,%3};"
        : "+f"(c[0]), "+f"(c[1]), "+f"(c[2]), "+f"(c[3])
        : "r"(a[0]), "r"(a[1]), "r"(a[2]), "r"(a[3]), "r"(b0), "r"(b1));
}

#define LDSM4(r0, r1, r2, r3, addr) \
    asm volatile("ldmatrix.sync.aligned.m8n8.x4.shared.b16 {%0,%1,%2,%3}, [%4];" \
                 : "=r"(r0), "=r"(r1), "=r"(r2), "=r"(r3) : "r"(addr))
#define LDSM4T(r0, r1, r2, r3, addr) \
    asm volatile("ldmatrix.sync.aligned.m8n8.x4.trans.shared.b16 {%0,%1,%2,%3}, [%4];" \
                 : "=r"(r0), "=r"(r1), "=r"(r2), "=r"(r3) : "r"(addr))

#define SM_BIAS 0
#define SM_AHI  512
#define SM_ALO  (512 + 18432)
#define SM_BHI  (18944 + 18432)
#define SM_BLO  (37376 + 17408)
#define SM_CACC (54784 + 17408)
#define SM_TOT  (72192 + 512)
#define ASTRIDE 72
#define BSTRIDE 136

// D[128x128] = A[128 x K_TOT] @ Wg[K_TOT x 128], fp32 acc.
template <int K_TOT, int SEM>
__device__ __forceinline__ void gemm_body(int bx, int m, const float* __restrict__ A,
                                          const __half* __restrict__ A16,
                                          const float* __restrict__ Wg,
                                          const float* __restrict__ bias, char* smem) {
    float* shb = (float*)(smem + SM_BIAS);
    float* colacc = (float*)(smem + SM_CACC);
    int tid = threadIdx.x;
    int wid = tid >> 5, lane = tid & 31;
    int wr = wid >> 1, wc = wid & 1;
    int rowbase = bx * 128;

    if (tid < 128) {
        shb[tid] = bias[tid];
        if (SEM) colacc[tid] = 0.f;
    }

    uint32_t sa_hi = smem_u32(smem + SM_AHI);
    uint32_t sa_lo = smem_u32(smem + SM_ALO);
    uint32_t sb_hi = smem_u32(smem + SM_BHI);
    uint32_t sb_lo = smem_u32(smem + SM_BLO);

    float acc[2][8][4];
#pragma unroll
    for (int i = 0; i < 2; i++)
#pragma unroll
        for (int j = 0; j < 8; j++)
#pragma unroll
            for (int k = 0; k < 4; k++) acc[i][j][k] = 0.f;

    int li = lane >> 3, lr = lane & 7;
    int a_row_off = (li & 1) * 8 + lr;
    int a_col_off = (li >> 1) * 8;
    int b_row_off = (li & 1) * 8 + lr;
    int b_col_off = (li >> 1) * 8;

    const int NCH = K_TOT / 64;
    for (int ch = 0; ch < NCH; ch++) {
        if (ch) __syncthreads();
#pragma unroll
        for (int i = 0; i < 8; i++) {
            int f = tid + i * 256;
            int r = f >> 4, c4 = f & 15;
            int gn = rowbase + r;
            float4 v = make_float4(0.f, 0.f, 0.f, 0.f);
            if (gn < NN) {
                if (SEM) {
                    uint2 u = *(const uint2*)(A16 + (size_t)gn * K_TOT + ch * 64 + c4 * 4);
                    float2 f0 = __half22float2(*reinterpret_cast<__half2*>(&u.x));
                    float2 f1 = __half22float2(*reinterpret_cast<__half2*>(&u.y));
                    v = make_float4(f0.x, f0.y, f1.x, f1.y);
                } else {
                    v = *(const float4*)(A + (size_t)gn * K_TOT + ch * 64 + c4 * 4);
                }
            }
            __nv_bfloat16 h0 = __float2bfloat16(v.x), h1 = __float2bfloat16(v.y);
            __nv_bfloat16 h2 = __float2bfloat16(v.z), h3 = __float2bfloat16(v.w);
            uint32_t off = (r * ASTRIDE + c4 * 4) * 2;
            __nv_bfloat162* ph = (__nv_bfloat162*)(smem + SM_AHI + off);
            ph[0] = __nv_bfloat162(h0, h1);
            ph[1] = __nv_bfloat162(h2, h3);
            if (!SEM) {
                __nv_bfloat16 l0 = __float2bfloat16(v.x - __bfloat162float(h0));
                __nv_bfloat16 l1 = __float2bfloat16(v.y - __bfloat162float(h1));
                __nv_bfloat16 l2 = __float2bfloat16(v.z - __bfloat162float(h2));
                __nv_bfloat16 l3 = __float2bfloat16(v.w - __bfloat162float(h3));
                __nv_bfloat162* pl = (__nv_bfloat162*)(smem + SM_ALO + off);
                pl[0] = __nv_bfloat162(l0, l1);
                pl[1] = __nv_bfloat162(l2, l3);
            }
        }
#pragma unroll
        for (int i = 0; i < 8; i++) {
            int f = tid + i * 256;
            int k = f >> 5, n4 = f & 31;
            float4 v = *(const float4*)(Wg + (size_t)(ch * 64 + k) * 128 + n4 * 4);
            __nv_bfloat16 h0 = __float2bfloat16(v.x), h1 = __float2bfloat16(v.y);
            __nv_bfloat16 h2 = __float2bfloat16(v.z), h3 = __float2bfloat16(v.w);
            __nv_bfloat16 l0 = __float2bfloat16(v.x - __bfloat162float(h0));
            __nv_bfloat16 l1 = __float2bfloat16(v.y - __bfloat162float(h1));
            __nv_bfloat16 l2 = __float2bfloat16(v.z - __bfloat162float(h2));
            __nv_bfloat16 l3 = __float2bfloat16(v.w - __bfloat162float(h3));
            uint32_t off = (k * BSTRIDE + n4 * 4) * 2;
            __nv_bfloat162* ph = (__nv_bfloat162*)(smem + SM_BHI + off);
            ph[0] = __nv_bfloat162(h0, h1);
            ph[1] = __nv_bfloat162(h2, h3);
            __nv_bfloat162* pl = (__nv_bfloat162*)(smem + SM_BLO + off);
            pl[0] = __nv_bfloat162(l0, l1);
            pl[1] = __nv_bfloat162(l2, l3);
        }
        __syncthreads();

#pragma unroll
        for (int ks = 0; ks < 4; ks++) {
            uint32_t ah[2][4], al[2][4];
#pragma unroll
            for (int mt = 0; mt < 2; mt++) {
                int row0 = wr * 32 + mt * 16;
                uint32_t aoff = ((row0 + a_row_off) * ASTRIDE + ks * 16 + a_col_off) * 2;
                LDSM4(ah[mt][0], ah[mt][1], ah[mt][2], ah[mt][3], sa_hi + aoff);
                if (!SEM) LDSM4(al[mt][0], al[mt][1], al[mt][2], al[mt][3], sa_lo + aoff);
            }
#pragma unroll
            for (int nt = 0; nt < 4; nt++) {
                int n0 = wc * 64 + nt * 16;
                uint32_t boff = ((ks * 16 + b_row_off) * BSTRIDE + n0 + b_col_off) * 2;
                uint32_t bh0, bh1, bh2, bh3, bl0, bl1, bl2, bl3;
                LDSM4T(bh0, bh1, bh2, bh3, sb_hi + boff);
                LDSM4T(bl0, bl1, bl2, bl3, sb_lo + boff);
#pragma unroll
                for (int mt = 0; mt < 2; mt++) {
                    mma_bf16(acc[mt][nt * 2],     ah[mt], bh0, bh1);
                    mma_bf16(acc[mt][nt * 2 + 1], ah[mt], bh2, bh3);
                    if (!SEM) {
                        mma_bf16(acc[mt][nt * 2],     al[mt], bh0, bh1);
                        mma_bf16(acc[mt][nt * 2 + 1], al[mt], bh2, bh3);
                    }
                    mma_bf16(acc[mt][nt * 2],     ah[mt], bl0, bl1);
                    mma_bf16(acc[mt][nt * 2 + 1], ah[mt], bl2, bl3);
                }
            }
        }
    }

    int g = lane >> 2, t = lane & 3;
    if (!SEM) {
#pragma unroll
        for (int mt = 0; mt < 2; mt++)
#pragma unroll
            for (int n8 = 0; n8 < 8; n8++) {
                int row = rowbase + wr * 32 + mt * 16 + g;
                int col = wc * 64 + n8 * 8 + t * 2;
                float b0 = shb[col], b1 = shb[col + 1];
                if (row < NN) {
                    float2 o = make_float2(acc[mt][n8][0] + b0, acc[mt][n8][1] + b1);
                    *(float2*)&g_xp[(size_t)row * 128 + col] = o;
                    *(__half2*)&g_xp16[(size_t)row * 128 + col] = __floats2half2_rn(o.x, o.y);
                }
                if (row + 8 < NN) {
                    float2 o = make_float2(acc[mt][n8][2] + b0, acc[mt][n8][3] + b1);
                    *(float2*)&g_xp[(size_t)(row + 8) * 128 + col] = o;
                    *(__half2*)&g_xp16[(size_t)(row + 8) * 128 + col] = __floats2half2_rn(o.x, o.y);
                }
            }
    } else {
#pragma unroll
        for (int mt = 0; mt < 2; mt++)
#pragma unroll
            for (int n8 = 0; n8 < 8; n8++) {
                int row0 = rowbase + wr * 32 + mt * 16 + g;
                int row1 = row0 + 8;
                int col = wc * 64 + n8 * 8 + t * 2;
                float b0 = shb[col], b1 = shb[col + 1];
                float t0 = (row0 < NN) ? ftanh(acc[mt][n8][0] + b0) : 0.f;
                float t1 = (row0 < NN) ? ftanh(acc[mt][n8][1] + b1) : 0.f;
                if (row1 < NN) {
                    t0 += ftanh(acc[mt][n8][2] + b0);
                    t1 += ftanh(acc[mt][n8][3] + b1);
                }
#pragma unroll
                for (int o = 4; o <= 16; o <<= 1) {
                    t0 += __shfl_xor_sync(0xffffffffu, t0, o);
                    t1 += __shfl_xor_sync(0xffffffffu, t1, o);
                }
                if (g == 0) {
                    atomicAdd(&colacc[col], t0);
                    atomicAdd(&colacc[col + 1], t1);
                }
            }
        __syncthreads();
        if (tid < 128) atomicAdd(&g_ksum[m * 128 + tid], colacc[tid]);
    }
}

// ------------------------- init -------------------------
__global__ void k_init(const void* e0) {
    if (blockIdx.x == 0) {
        __shared__ int bad;
        if (threadIdx.x == 0) bad = 0;
        __syncthreads();
        const long long* p = (const long long*)e0;
        int b = 0;
        for (int i = threadIdx.x; i < 1024; i += blockDim.x) {
            long long v = p[i];
            if (v < 0 || v >= NN) b = 1;
        }
        if (b) atomicOr(&bad, 1);
        __syncthreads();
        if (threadIdx.x == 0) g_f64 = bad ? 0 : 1;
    } else {
        int i = (blockIdx.x - 1) * 256 + threadIdx.x;
        if (i < 2 * NN) (&g_deg[0][0])[i] = 0;
        if (i < 2 * HID) g_ksum[i] = 0.f;
    }
}

// ------------------------- projection GEMM wrapper -------------------------
__global__ void __launch_bounds__(256) k_proj(const float* __restrict__ x,
                                              const float* __restrict__ pw,
                                              const float* __restrict__ pb) {
    extern __shared__ char smem[];
    gemm_body<256, 0>(blockIdx.x, 0, x, (const __half*)0, pw, pb, smem);
}

// ------------------------- hist -------------------------
__global__ void k_hist(const void* e0, const void* e1) {
    long long i = blockIdx.x * (long long)blockDim.x + threadIdx.x;
    if (i >= 2LL * NE) return;
    int m = (i >= NE) ? 1 : 0;
    long long j = i - (long long)m * NE;
    const void* p = m ? e1 : e0;
    int dst = g_f64 ? (int)((const long long*)p)[NE + j] : ((const int*)p)[NE + j];
    atomicAdd(&g_deg[m][dst], 1);
}

// ------------------------- scans -------------------------
__global__ void k_scanA() {
    __shared__ int s[SCAN_B];
    int m = blockIdx.y;
    int b = blockIdx.x;
    int t = threadIdx.x;
    int gi = b * SCAN_B + t;
    int val = (gi < NN) ? g_deg[m][gi] : 0;
    s[t] = val;
    __syncthreads();
#pragma unroll
    for (int off = 1; off < SCAN_B; off <<= 1) {
        int v = (t >= off) ? s[t - off] : 0;
        __syncthreads();
        s[t] += v;
        __syncthreads();
    }
    if (gi < NN) g_off[m][gi] = s[t] - val;
    if (t == SCAN_B - 1) g_bsum[m][b] = s[t];
}

__global__ void k_scanB() {
    __shared__ int s[128];
    int m = blockIdx.x;
    int t = threadIdx.x;
    int v = (t < NB) ? g_bsum[m][t] : 0;
    s[t] = v;
    __syncthreads();
#pragma unroll
    for (int off = 1; off < 128; off <<= 1) {
        int u = (t >= off) ? s[t - off] : 0;
        __syncthreads();
        s[t] += u;
        __syncthreads();
    }
    if (t < NB) g_boff[m][t] = s[t] - v;
    if (t == 127) g_boff[m][NB] = s[127];
}

__global__ void k_scanC() {
    int m = blockIdx.y;
    int i = blockIdx.x * blockDim.x + threadIdx.x;
    if (i >= NN) return;
    int off = g_off[m][i] + g_boff[m][i >> 10];
    g_off[m][i] = off;
    g_cur[m][i] = off;
    if (i == 0) g_off[m][NN] = g_boff[m][NB];
}

// ------------------------- scatter (CSR fill) -------------------------
__global__ void __launch_bounds__(256) k_scatter(const void* e0, const void* e1) {
    int f64 = g_f64;
#pragma unroll
    for (int r = 0; r < 4; r++) {
        long long i = (long long)blockIdx.x * 1024 + r * 256 + threadIdx.x;
        if (i < 2LL * NE) {
            int m = (i >= NE) ? 1 : 0;
            long long j = i - (long long)m * NE;
            const void* p = m ? e1 : e0;
            int src, dst;
            if (f64) {
                src = (int)((const long long*)p)[j];
                dst = (int)((const long long*)p)[NE + j];
            } else {
                src = ((const int*)p)[j];
                dst = ((const int*)p)[NE + j];
            }
            int pos = atomicAdd(&g_cur[m][dst], 1);
            g_srcs[m][pos] = src;
        }
    }
}

// ------------------------- per-node attention logits -------------------------
__global__ void k_alpha(const float* __restrict__ as0, const float* __restrict__ ad0,
                        const float* __restrict__ as1, const float* __restrict__ ad1) {
    __shared__ float a[4][128];
    int tid = threadIdx.x;
    if (tid < 128) {
        a[0][tid] = as0[tid];
        a[1][tid] = ad0[tid];
        a[2][tid] = as1[tid];
        a[3][tid] = ad1[tid];
    }
    __syncthreads();
    int n = blockIdx.x * blockDim.x + tid;
    if (n >= NN) return;
    float r[4][8];
#pragma unroll
    for (int t = 0; t < 4; t++)
#pragma unroll
        for (int h = 0; h < 8; h++) r[t][h] = 0.f;
    const float4* xp4 = (const float4*)&g_xp[(size_t)n * 128];
#pragma unroll
    for (int j4 = 0; j4 < 32; j4++) {
        float4 v = xp4[j4];
        int j = j4 * 4;
        int h = j >> 4;
        float c[4] = {v.x, v.y, v.z, v.w};
#pragma unroll
        for (int cc = 0; cc < 4; cc++)
#pragma unroll
            for (int t = 0; t < 4; t++) r[t][h] = fmaf(c[cc], a[t][j + cc], r[t][h]);
    }
    *(float4*)&g_as[0][n * 8]     = make_float4(r[0][0], r[0][1], r[0][2], r[0][3]);
    *(float4*)&g_as[0][n * 8 + 4] = make_float4(r[0][4], r[0][5], r[0][6], r[0][7]);
    *(float4*)&g_ad[0][n * 8]     = make_float4(r[1][0], r[1][1], r[1][2], r[1][3]);
    *(float4*)&g_ad[0][n * 8 + 4] = make_float4(r[1][4], r[1][5], r[1][6], r[1][7]);
    *(float4*)&g_as[1][n * 8]     = make_float4(r[2][0], r[2][1], r[2][2], r[2][3]);
    *(float4*)&g_as[1][n * 8 + 4] = make_float4(r[2][4], r[2][5], r[2][6], r[2][7]);
    *(float4*)&g_ad[1][n * 8]     = make_float4(r[3][0], r[3][1], r[3][2], r[3][3]);
    *(float4*)&g_ad[1][n * 8 + 4] = make_float4(r[3][4], r[3][5], r[3][6], r[3][7]);
}

// --------- fused edge kernel: exp+denom (smem-staged) then fp16 aggregate (8-wide MLP) ---------
__device__ __forceinline__ float4 ld_xp16(int s, int lane) {
    uint2 u = *(const uint2*)&g_xp16[(size_t)s * 128 + lane * 4];
    float2 f0 = __half22float2(*reinterpret_cast<__half2*>(&u.x));
    float2 f1 = __half22float2(*reinterpret_cast<__half2*>(&u.y));
    return make_float4(f0.x, f0.y, f1.x, f1.y);
}

__global__ void __launch_bounds__(256) k_edge() {
    __shared__ float exbuf[8][EDGE_CAP * 8];   // 16KB
    int m = blockIdx.y;
    int w = (blockIdx.x * blockDim.x + threadIdx.x) >> 5;
    int wl = threadIdx.x >> 5;
    int lane = threadIdx.x & 31;
    if (w >= NN) return;
    int beg = g_off[m][w], end = g_off[m][w + 1];
    int deg = end - beg;
    bool fits = (deg <= EDGE_CAP);

    float4 ad0 = *(const float4*)&g_ad[m][w * 8];
    float4 ad1 = *(const float4*)&g_ad[m][w * 8 + 4];
    float den[8];
#pragma unroll
    for (int h = 0; h < 8; h++) den[h] = 0.f;
    for (int e = beg + lane; e < end; e += 32) {
        int src = g_srcs[m][e];
        float4 s0 = *(const float4*)&g_as[m][src * 8];
        float4 s1 = *(const float4*)&g_as[m][src * 8 + 4];
        float t[8] = {s0.x + ad0.x, s0.y + ad0.y, s0.z + ad0.z, s0.w + ad0.w,
                      s1.x + ad1.x, s1.y + ad1.y, s1.z + ad1.z, s1.w + ad1.w};
        float ex[8];
#pragma unroll
        for (int h = 0; h < 8; h++) {
            float l = t[h] > 0.f ? t[h] : 0.2f * t[h];
            ex[h] = fexp(l);
            den[h] += ex[h];
        }
        if (fits) {
            float* dst = &exbuf[wl][(e - beg) * 8];
            *(float4*)dst       = make_float4(ex[0], ex[1], ex[2], ex[3]);
            *(float4*)(dst + 4) = make_float4(ex[4], ex[5], ex[6], ex[7]);
        } else {
            *(float4*)&g_e[m][(size_t)e * 8]     = make_float4(ex[0], ex[1], ex[2], ex[3]);
            *(float4*)&g_e[m][(size_t)e * 8 + 4] = make_float4(ex[4], ex[5], ex[6], ex[7]);
        }
    }
#pragma unroll
    for (int h = 0; h < 8; h++)
#pragma unroll
        for (int o = 16; o > 0; o >>= 1) den[h] += __shfl_xor_sync(0xffffffffu, den[h], o);
    __syncwarp();

    int h = lane >> 2;
    float iv = __fdividef(1.f, den[h] + 1e-16f);
    float4 acc = make_float4(0.f, 0.f, 0.f, 0.f);
    const int* sb = g_srcs[m];
    if (fits) {
        const float* xb = exbuf[wl];
        int j = 0;
        for (; j + 8 <= deg; j += 8) {
            int e = beg + j;
            int s[8];
            float xw[8];
            float4 v[8];
#pragma unroll
            for (int u = 0; u < 8; u++) s[u] = sb[e + u];
#pragma unroll
            for (int u = 0; u < 8; u++) xw[u] = xb[(j + u) * 8 + h];
#pragma unroll
            for (int u = 0; u < 8; u++) v[u] = ld_xp16(s[u], lane);
#pragma unroll
            for (int u = 0; u < 8; u++) {
                acc.x = fmaf(v[u].x, xw[u], acc.x);
                acc.y = fmaf(v[u].y, xw[u], acc.y);
                acc.z = fmaf(v[u].z, xw[u], acc.z);
                acc.w = fmaf(v[u].w, xw[u], acc.w);
            }
        }
        for (; j < deg; j++) {
            int s0 = sb[beg + j];
            float x0 = xb[j * 8 + h];
            float4 v0 = ld_xp16(s0, lane);
            acc.x = fmaf(v0.x, x0, acc.x); acc.y = fmaf(v0.y, x0, acc.y);
            acc.z = fmaf(v0.z, x0, acc.z); acc.w = fmaf(v0.w, x0, acc.w);
        }
    } else {
        const float* eb = g_e[m];
        for (int e = beg; e < end; e++) {
            int s0 = sb[e];
            float x0 = eb[(size_t)e * 8 + h];
            float4 v0 = ld_xp16(s0, lane);
            acc.x = fmaf(v0.x, x0, acc.x); acc.y = fmaf(v0.y, x0, acc.y);
            acc.z = fmaf(v0.z, x0, acc.z); acc.w = fmaf(v0.w, x0, acc.w);
        }
    }
    float2 o01 = make_float2(fmaxf(acc.x * iv, 0.f), fmaxf(acc.y * iv, 0.f));
    float2 o23 = make_float2(fmaxf(acc.z * iv, 0.f), fmaxf(acc.w * iv, 0.f));
    uint2 st;
    *reinterpret_cast<__half2*>(&st.x) = __floats2half2_rn(o01.x, o01.y);
    *reinterpret_cast<__half2*>(&st.y) = __floats2half2_rn(o23.x, o23.y);
    *(uint2*)&g_acc16[m][(size_t)w * 128 + lane * 4] = st;
}

// ------------------------- semantic GEMM wrapper -------------------------
__global__ void __launch_bounds__(256) k_sem(const float* __restrict__ kw,
                                             const float* __restrict__ kb) {
    extern __shared__ char smem[];
    int m = blockIdx.y;
    gemm_body<128, 1>(blockIdx.x, m, (const float*)0, g_acc16[m], kw, kb, smem);
}

// ------------------------- semantic softmax -------------------------
__global__ void k_attn(const float* __restrict__ q) {
    int j = threadIdx.x;
    __shared__ float red[8];
    float qv = q[j];
    float s0 = g_ksum[j] * qv;
    float s1 = g_ksum[128 + j] * qv;
#pragma unroll
    for (int o = 16; o > 0; o >>= 1) {
        s0 += __shfl_xor_sync(0xffffffffu, s0, o);
        s1 += __shfl_xor_sync(0xffffffffu, s1, o);
    }
    int lane = j & 31, wid = j >> 5;
    if (lane == 0) {
        red[wid] = s0;
        red[4 + wid] = s1;
    }
    __syncthreads();
    if (j == 0) {
        float t0 = (red[0] + red[1] + red[2] + red[3]) / (float)NN;
        float t1 = (red[4] + red[5] + red[6] + red[7]) / (float)NN;
        float mx = fmaxf(t0, t1);
        float e0 = fexp(t0 - mx), e1 = fexp(t1 - mx);
        float inv = __fdividef(1.f, e0 + e1);
        g_attn[0] = e0 * inv;
        g_attn[1] = e1 * inv;
    }
}

// ------------------------- fused output linear (fp16 g_acc16 inputs) -------------------------
__global__ void k_final(const float* __restrict__ lw, const float* __restrict__ lb,
                        float* __restrict__ out) {
    __shared__ float ws[512];
    __shared__ float bs[4];
    int tid = threadIdx.x;
    ws[tid] = lw[tid];
    ws[tid + 256] = lw[tid + 256];
    if (tid < 4) bs[tid] = lb[tid];
    __syncthreads();
    int n = blockIdx.x * blockDim.x + tid;
    if (n >= NN) return;
    float a0 = g_attn[0], a1 = g_attn[1];
    float o0 = bs[0], o1 = bs[1], o2 = bs[2], o3 = bs[3];
    const uint2* p0 = (const uint2*)&g_acc16[0][(size_t)n * 128];
    const uint2* p1 = (const uint2*)&g_acc16[1][(size_t)n * 128];
#pragma unroll 8
    for (int j4 = 0; j4 < 32; j4++) {
        uint2 u0 = p0[j4];
        uint2 u1 = p1[j4];
        float2 a00 = __half22float2(*reinterpret_cast<__half2*>(&u0.x));
        float2 a01 = __half22float2(*reinterpret_cast<__half2*>(&u0.y));
        float2 a10 = __half22float2(*reinterpret_cast<__half2*>(&u1.x));
        float2 a11 = __half22float2(*reinterpret_cast<__half2*>(&u1.y));
        float c0[4] = {a00.x, a00.y, a01.x, a01.y};
        float c1[4] = {a10.x, a10.y, a11.x, a11.y};
#pragma unroll
        for (int jj = 0; jj < 4; jj++) {
            float f = fmaf(a0, c0[jj], a1 * c1[jj]);
            int j = j4 * 4 + jj;
            o0 = fmaf(f, ws[j * 4 + 0], o0);
            o1 = fmaf(f, ws[j * 4 + 1], o1);
            o2 = fmaf(f, ws[j * 4 + 2], o2);
            o3 = fmaf(f, ws[j * 4 + 3], o3);
        }
    }
    *(float4*)(out + (size_t)n * 4) = make_float4(o0, o1, o2, o3);
}

// ------------------------- launch -------------------------
extern "C" void kernel_launch(void* const* d_in, const int* in_sizes, int n_in,
                              void* d_out, int out_size) {
    const float* x   = (const float*)d_in[0];
    const void*  e0  = d_in[1];
    const void*  e1  = d_in[2];
    const float* pw  = (const float*)d_in[3];
    const float* pb  = (const float*)d_in[4];
    const float* as0 = (const float*)d_in[5];
    const float* ad0 = (const float*)d_in[6];
    const float* as1 = (const float*)d_in[7];
    const float* ad1 = (const float*)d_in[8];
    const float* kw  = (const float*)d_in[9];
    const float* kb  = (const float*)d_in[10];
    const float* q   = (const float*)d_in[11];
    const float* lw  = (const float*)d_in[12];
    const float* lb  = (const float*)d_in[13];
    float* out = (float*)d_out;

    cudaFuncSetAttribute(k_proj, cudaFuncAttributeMaxDynamicSharedMemorySize, SM_TOT);
    cudaFuncSetAttribute(k_sem, cudaFuncAttributeMaxDynamicSharedMemorySize, SM_TOT);

    bool fork = g_sok;
    if (fork) {
        // fork: proj + alpha concurrently with the CSR build chain
        cudaEventRecord(g_evf, 0);
        cudaStreamWaitEvent(g_side, g_evf, 0);
        k_proj<<<GB, 256, SM_TOT, g_side>>>(x, pw, pb);
        k_alpha<<<(NN + 255) / 256, 256, 0, g_side>>>(as0, ad0, as1, ad1);
        cudaEventRecord(g_evj, g_side);
    }

    k_init<<<1 + (2 * NN + 255) / 256, 256>>>(e0);
    k_hist<<<(2 * NE + 255) / 256, 256>>>(e0, e1);
    dim3 gsA(NB, 2);
    k_scanA<<<gsA, SCAN_B>>>();
    k_scanB<<<2, 128>>>();
    dim3 gsC((NN + 255) / 256, 2);
    k_scanC<<<gsC, 256>>>();
    k_scatter<<<NSCAT, 256>>>(e0, e1);

    if (fork) {
        cudaStreamWaitEvent(0, g_evj, 0);   // join: g_xp/g_xp16/g_as/g_ad ready
    } else {
        k_proj<<<GB, 256, SM_TOT>>>(x, pw, pb);
        k_alpha<<<(NN + 255) / 256, 256>>>(as0, ad0, as1, ad1);
    }
    dim3 ge((NN * 32 + 255) / 256, 2);
    k_edge<<<ge, 256>>>();
    dim3 gg(GB, 2);
    k_sem<<<gg, 256, SM_TOT>>>(kw, kb);
    k_attn<<<1, 128>>>(q);
    k_final<<<(NN + 255) / 256, 256>>>(lw, lb, out);
}

// round 17
// speedup vs baseline: 1.0300x; 1.0300x over previous
#include <cuda_runtime.h>
#include <cuda_bf16.h>
#include <cuda_fp16.h>
#include <cstdint>

#define NN 100000
#define NE 1600000
#define HEADS 8
#define HID 128
#define SCAN_B 1024
#define NB ((NN + SCAN_B - 1) / SCAN_B)   // 98
#define EDGE_CAP 64
#define NSCAT 3125                         // 3125*1024 >= 2*NE
#define GB ((NN + 127) / 128)              // 782 gemm row-blocks

// ------------------------- static scratch (no allocation) -------------------------
static __device__ float  g_xp[(size_t)NN * HID];
static __device__ __half g_xp16[(size_t)NN * HID];    // fp16 mirror for edge gathers
static __device__ float  g_as[2][NN * HEADS];
static __device__ float  g_ad[2][NN * HEADS];
static __device__ float  g_e[2][(size_t)NE * HEADS];  // spill only (deg > EDGE_CAP)
static __device__ int    g_srcs[2][NE];
static __device__ int    g_deg[2][NN];
static __device__ int    g_off[2][NN + 1];
static __device__ int    g_cur[2][NN];
static __device__ int    g_bsum[2][NB];
static __device__ int    g_boff[2][NB + 1];
static __device__ __half g_acc16[2][(size_t)NN * HID]; // fp16 aggregated outputs
static __device__ float  g_ksum[2 * HID];
static __device__ float  g_attn[2];
static __device__ int    g_f64;

// ------------------------- side stream for graph-level parallelism -------------------------
static cudaStream_t g_side = 0;
static cudaEvent_t  g_evf = 0, g_evj = 0;
static bool g_sok = false;
namespace {
struct SInit {
    SInit() {
        g_sok = (cudaStreamCreateWithFlags(&g_side, cudaStreamNonBlocking) == cudaSuccess) &&
                (cudaEventCreateWithFlags(&g_evf, cudaEventDisableTiming) == cudaSuccess) &&
                (cudaEventCreateWithFlags(&g_evj, cudaEventDisableTiming) == cudaSuccess);
    }
};
static SInit s_sinit;
}

// ------------------------- math helpers -------------------------
__device__ __forceinline__ float fexp(float x) {
    float y = x * 1.4426950408889634f;
    float r = rintf(y);
    float f = y - r;
    float p = 1.33336498e-3f;
    p = fmaf(p, f, 9.61011201e-3f);
    p = fmaf(p, f, 5.55040678e-2f);
    p = fmaf(p, f, 2.40226507e-1f);
    p = fmaf(p, f, 6.93147182e-1f);
    p = fmaf(p, f, 1.0f);
    int ir = (int)r;
    ir = ir < -120 ? -120 : (ir > 120 ? 120 : ir);
    return __int_as_float((ir + 127) << 23) * p;
}

__device__ __forceinline__ float ftanh(float x) {
    float cx = fminf(fmaxf(x, -9.f), 9.f);
    float x2 = cx * cx;
    float p = -2.76076847742355e-16f;
    p = fmaf(p, x2, 2.00018790482477e-13f);
    p = fmaf(p, x2, -8.60467152213735e-11f);
    p = fmaf(p, x2, 5.12229709037114e-08f);
    p = fmaf(p, x2, 1.48572235717979e-05f);
    p = fmaf(p, x2, 6.37261928875436e-04f);
    p = fmaf(p, x2, 4.89352455891786e-03f);
    p = p * cx;
    float q = 1.19825839466702e-06f;
    q = fmaf(q, x2, 1.18534705686654e-04f);
    q = fmaf(q, x2, 2.26843463243900e-03f);
    q = fmaf(q, x2, 4.89352518554385e-03f);
    return __fdividef(p, q);
}

// ------------------------- warp-MMA helpers -------------------------
__device__ __forceinline__ uint32_t smem_u32(const void* p) {
    uint32_t a;
    asm("{ .reg .u64 t; cvta.to.shared.u64 t, %1; cvt.u32.u64 %0, t; }" : "=r"(a) : "l"(p));
    return a;
}

__device__ __forceinline__ void mma_bf16(float* c, const uint32_t* a, uint32_t b0, uint32_t b1) {
    asm volatile(
        "mma.sync.aligned.m16n8k16.row.col.f32.bf16.bf16.f32 "
        "{%0,%1,%2,%3}, {%4,%5,%6,%7}, {%8,%9}, {%0,%1,%2,%3};"
        : "+f"(c[0]), "+f"(c[1]), "+f"(c[2]), "+f"(c[3])
        : "r"(a[0]), "r"(a[1]), "r"(a[2]), "r"(a[3]), "r"(b0), "r"(b1));
}

#define LDSM4(r0, r1, r2, r3, addr) \
    asm volatile("ldmatrix.sync.aligned.m8n8.x4.shared.b16 {%0,%1,%2,%3}, [%4];" \
                 : "=r"(r0), "=r"(r1), "=r"(r2), "=r"(r3) : "r"(addr))
#define LDSM4T(r0, r1, r2, r3, addr) \
    asm volatile("ldmatrix.sync.aligned.m8n8.x4.trans.shared.b16 {%0,%1,%2,%3}, [%4];" \
                 : "=r"(r0), "=r"(r1), "=r"(r2), "=r"(r3) : "r"(addr))

#define SM_BIAS 0
#define SM_AHI  512
#define SM_ALO  (512 + 18432)
#define SM_BHI  (18944 + 18432)
#define SM_BLO  (37376 + 17408)
#define SM_CACC (54784 + 17408)
#define SM_TOT  (72192 + 512)
#define ASTRIDE 72
#define BSTRIDE 136

// D[128x128] = A[128 x K_TOT] @ Wg[K_TOT x 128], fp32 acc.
template <int K_TOT, int SEM>
__device__ __forceinline__ void gemm_body(int bx, int m, const float* __restrict__ A,
                                          const __half* __restrict__ A16,
                                          const float* __restrict__ Wg,
                                          const float* __restrict__ bias, char* smem) {
    float* shb = (float*)(smem + SM_BIAS);
    float* colacc = (float*)(smem + SM_CACC);
    int tid = threadIdx.x;
    int wid = tid >> 5, lane = tid & 31;
    int wr = wid >> 1, wc = wid & 1;
    int rowbase = bx * 128;

    if (tid < 128) {
        shb[tid] = bias[tid];
        if (SEM) colacc[tid] = 0.f;
    }

    uint32_t sa_hi = smem_u32(smem + SM_AHI);
    uint32_t sa_lo = smem_u32(smem + SM_ALO);
    uint32_t sb_hi = smem_u32(smem + SM_BHI);
    uint32_t sb_lo = smem_u32(smem + SM_BLO);

    float acc[2][8][4];
#pragma unroll
    for (int i = 0; i < 2; i++)
#pragma unroll
        for (int j = 0; j < 8; j++)
#pragma unroll
            for (int k = 0; k < 4; k++) acc[i][j][k] = 0.f;

    int li = lane >> 3, lr = lane & 7;
    int a_row_off = (li & 1) * 8 + lr;
    int a_col_off = (li >> 1) * 8;
    int b_row_off = (li & 1) * 8 + lr;
    int b_col_off = (li >> 1) * 8;

    const int NCH = K_TOT / 64;
    for (int ch = 0; ch < NCH; ch++) {
        if (ch) __syncthreads();
#pragma unroll
        for (int i = 0; i < 8; i++) {
            int f = tid + i * 256;
            int r = f >> 4, c4 = f & 15;
            int gn = rowbase + r;
            float4 v = make_float4(0.f, 0.f, 0.f, 0.f);
            if (gn < NN) {
                if (SEM) {
                    uint2 u = *(const uint2*)(A16 + (size_t)gn * K_TOT + ch * 64 + c4 * 4);
                    float2 f0 = __half22float2(*reinterpret_cast<__half2*>(&u.x));
                    float2 f1 = __half22float2(*reinterpret_cast<__half2*>(&u.y));
                    v = make_float4(f0.x, f0.y, f1.x, f1.y);
                } else {
                    v = *(const float4*)(A + (size_t)gn * K_TOT + ch * 64 + c4 * 4);
                }
            }
            __nv_bfloat16 h0 = __float2bfloat16(v.x), h1 = __float2bfloat16(v.y);
            __nv_bfloat16 h2 = __float2bfloat16(v.z), h3 = __float2bfloat16(v.w);
            uint32_t off = (r * ASTRIDE + c4 * 4) * 2;
            __nv_bfloat162* ph = (__nv_bfloat162*)(smem + SM_AHI + off);
            ph[0] = __nv_bfloat162(h0, h1);
            ph[1] = __nv_bfloat162(h2, h3);
            if (!SEM) {
                __nv_bfloat16 l0 = __float2bfloat16(v.x - __bfloat162float(h0));
                __nv_bfloat16 l1 = __float2bfloat16(v.y - __bfloat162float(h1));
                __nv_bfloat16 l2 = __float2bfloat16(v.z - __bfloat162float(h2));
                __nv_bfloat16 l3 = __float2bfloat16(v.w - __bfloat162float(h3));
                __nv_bfloat162* pl = (__nv_bfloat162*)(smem + SM_ALO + off);
                pl[0] = __nv_bfloat162(l0, l1);
                pl[1] = __nv_bfloat162(l2, l3);
            }
        }
#pragma unroll
        for (int i = 0; i < 8; i++) {
            int f = tid + i * 256;
            int k = f >> 5, n4 = f & 31;
            float4 v = *(const float4*)(Wg + (size_t)(ch * 64 + k) * 128 + n4 * 4);
            __nv_bfloat16 h0 = __float2bfloat16(v.x), h1 = __float2bfloat16(v.y);
            __nv_bfloat16 h2 = __float2bfloat16(v.z), h3 = __float2bfloat16(v.w);
            __nv_bfloat16 l0 = __float2bfloat16(v.x - __bfloat162float(h0));
            __nv_bfloat16 l1 = __float2bfloat16(v.y - __bfloat162float(h1));
            __nv_bfloat16 l2 = __float2bfloat16(v.z - __bfloat162float(h2));
            __nv_bfloat16 l3 = __float2bfloat16(v.w - __bfloat162float(h3));
            uint32_t off = (k * BSTRIDE + n4 * 4) * 2;
            __nv_bfloat162* ph = (__nv_bfloat162*)(smem + SM_BHI + off);
            ph[0] = __nv_bfloat162(h0, h1);
            ph[1] = __nv_bfloat162(h2, h3);
            __nv_bfloat162* pl = (__nv_bfloat162*)(smem + SM_BLO + off);
            pl[0] = __nv_bfloat162(l0, l1);
            pl[1] = __nv_bfloat162(l2, l3);
        }
        __syncthreads();

#pragma unroll
        for (int ks = 0; ks < 4; ks++) {
            uint32_t ah[2][4], al[2][4];
#pragma unroll
            for (int mt = 0; mt < 2; mt++) {
                int row0 = wr * 32 + mt * 16;
                uint32_t aoff = ((row0 + a_row_off) * ASTRIDE + ks * 16 + a_col_off) * 2;
                LDSM4(ah[mt][0], ah[mt][1], ah[mt][2], ah[mt][3], sa_hi + aoff);
                if (!SEM) LDSM4(al[mt][0], al[mt][1], al[mt][2], al[mt][3], sa_lo + aoff);
            }
#pragma unroll
            for (int nt = 0; nt < 4; nt++) {
                int n0 = wc * 64 + nt * 16;
                uint32_t boff = ((ks * 16 + b_row_off) * BSTRIDE + n0 + b_col_off) * 2;
                uint32_t bh0, bh1, bh2, bh3, bl0, bl1, bl2, bl3;
                LDSM4T(bh0, bh1, bh2, bh3, sb_hi + boff);
                LDSM4T(bl0, bl1, bl2, bl3, sb_lo + boff);
#pragma unroll
                for (int mt = 0; mt < 2; mt++) {
                    mma_bf16(acc[mt][nt * 2],     ah[mt], bh0, bh1);
                    mma_bf16(acc[mt][nt * 2 + 1], ah[mt], bh2, bh3);
                    if (!SEM) {
                        mma_bf16(acc[mt][nt * 2],     al[mt], bh0, bh1);
                        mma_bf16(acc[mt][nt * 2 + 1], al[mt], bh2, bh3);
                    }
                    mma_bf16(acc[mt][nt * 2],     ah[mt], bl0, bl1);
                    mma_bf16(acc[mt][nt * 2 + 1], ah[mt], bl2, bl3);
                }
            }
        }
    }

    int g = lane >> 2, t = lane & 3;
    if (!SEM) {
#pragma unroll
        for (int mt = 0; mt < 2; mt++)
#pragma unroll
            for (int n8 = 0; n8 < 8; n8++) {
                int row = rowbase + wr * 32 + mt * 16 + g;
                int col = wc * 64 + n8 * 8 + t * 2;
                float b0 = shb[col], b1 = shb[col + 1];
                if (row < NN) {
                    float2 o = make_float2(acc[mt][n8][0] + b0, acc[mt][n8][1] + b1);
                    *(float2*)&g_xp[(size_t)row * 128 + col] = o;
                    *(__half2*)&g_xp16[(size_t)row * 128 + col] = __floats2half2_rn(o.x, o.y);
                }
                if (row + 8 < NN) {
                    float2 o = make_float2(acc[mt][n8][2] + b0, acc[mt][n8][3] + b1);
                    *(float2*)&g_xp[(size_t)(row + 8) * 128 + col] = o;
                    *(__half2*)&g_xp16[(size_t)(row + 8) * 128 + col] = __floats2half2_rn(o.x, o.y);
                }
            }
    } else {
#pragma unroll
        for (int mt = 0; mt < 2; mt++)
#pragma unroll
            for (int n8 = 0; n8 < 8; n8++) {
                int row0 = rowbase + wr * 32 + mt * 16 + g;
                int row1 = row0 + 8;
                int col = wc * 64 + n8 * 8 + t * 2;
                float b0 = shb[col], b1 = shb[col + 1];
                float t0 = (row0 < NN) ? ftanh(acc[mt][n8][0] + b0) : 0.f;
                float t1 = (row0 < NN) ? ftanh(acc[mt][n8][1] + b1) : 0.f;
                if (row1 < NN) {
                    t0 += ftanh(acc[mt][n8][2] + b0);
                    t1 += ftanh(acc[mt][n8][3] + b1);
                }
#pragma unroll
                for (int o = 4; o <= 16; o <<= 1) {
                    t0 += __shfl_xor_sync(0xffffffffu, t0, o);
                    t1 += __shfl_xor_sync(0xffffffffu, t1, o);
                }
                if (g == 0) {
                    atomicAdd(&colacc[col], t0);
                    atomicAdd(&colacc[col + 1], t1);
                }
            }
        __syncthreads();
        if (tid < 128) atomicAdd(&g_ksum[m * 128 + tid], colacc[tid]);
    }
}

// ------------------------- init -------------------------
__global__ void k_init(const void* e0) {
    if (blockIdx.x == 0) {
        __shared__ int bad;
        if (threadIdx.x == 0) bad = 0;
        __syncthreads();
        const long long* p = (const long long*)e0;
        int b = 0;
        for (int i = threadIdx.x; i < 1024; i += blockDim.x) {
            long long v = p[i];
            if (v < 0 || v >= NN) b = 1;
        }
        if (b) atomicOr(&bad, 1);
        __syncthreads();
        if (threadIdx.x == 0) g_f64 = bad ? 0 : 1;
    } else {
        int i = (blockIdx.x - 1) * 256 + threadIdx.x;
        if (i < 2 * NN) (&g_deg[0][0])[i] = 0;
        if (i < 2 * HID) g_ksum[i] = 0.f;
    }
}

// ------------------------- projection GEMM wrapper -------------------------
__global__ void __launch_bounds__(256) k_proj(const float* __restrict__ x,
                                              const float* __restrict__ pw,
                                              const float* __restrict__ pb) {
    extern __shared__ char smem[];
    gemm_body<256, 0>(blockIdx.x, 0, x, (const __half*)0, pw, pb, smem);
}

// ------------------------- hist -------------------------
__global__ void k_hist(const void* e0, const void* e1) {
    long long i = blockIdx.x * (long long)blockDim.x + threadIdx.x;
    if (i >= 2LL * NE) return;
    int m = (i >= NE) ? 1 : 0;
    long long j = i - (long long)m * NE;
    const void* p = m ? e1 : e0;
    int dst = g_f64 ? (int)((const long long*)p)[NE + j] : ((const int*)p)[NE + j];
    atomicAdd(&g_deg[m][dst], 1);
}

// ------------------------- scans -------------------------
__global__ void k_scanA() {
    __shared__ int s[SCAN_B];
    int m = blockIdx.y;
    int b = blockIdx.x;
    int t = threadIdx.x;
    int gi = b * SCAN_B + t;
    int val = (gi < NN) ? g_deg[m][gi] : 0;
    s[t] = val;
    __syncthreads();
#pragma unroll
    for (int off = 1; off < SCAN_B; off <<= 1) {
        int v = (t >= off) ? s[t - off] : 0;
        __syncthreads();
        s[t] += v;
        __syncthreads();
    }
    if (gi < NN) g_off[m][gi] = s[t] - val;
    if (t == SCAN_B - 1) g_bsum[m][b] = s[t];
}

__global__ void k_scanB() {
    __shared__ int s[128];
    int m = blockIdx.x;
    int t = threadIdx.x;
    int v = (t < NB) ? g_bsum[m][t] : 0;
    s[t] = v;
    __syncthreads();
#pragma unroll
    for (int off = 1; off < 128; off <<= 1) {
        int u = (t >= off) ? s[t - off] : 0;
        __syncthreads();
        s[t] += u;
        __syncthreads();
    }
    if (t < NB) g_boff[m][t] = s[t] - v;
    if (t == 127) g_boff[m][NB] = s[127];
}

__global__ void k_scanC() {
    int m = blockIdx.y;
    int i = blockIdx.x * blockDim.x + threadIdx.x;
    if (i >= NN) return;
    int off = g_off[m][i] + g_boff[m][i >> 10];
    g_off[m][i] = off;
    g_cur[m][i] = off;
    if (i == 0) g_off[m][NN] = g_boff[m][NB];
}

// ------------------------- scatter (CSR fill) -------------------------
__global__ void __launch_bounds__(256) k_scatter(const void* e0, const void* e1) {
    int f64 = g_f64;
#pragma unroll
    for (int r = 0; r < 4; r++) {
        long long i = (long long)blockIdx.x * 1024 + r * 256 + threadIdx.x;
        if (i < 2LL * NE) {
            int m = (i >= NE) ? 1 : 0;
            long long j = i - (long long)m * NE;
            const void* p = m ? e1 : e0;
            int src, dst;
            if (f64) {
                src = (int)((const long long*)p)[j];
                dst = (int)((const long long*)p)[NE + j];
            } else {
                src = ((const int*)p)[j];
                dst = ((const int*)p)[NE + j];
            }
            int pos = atomicAdd(&g_cur[m][dst], 1);
            g_srcs[m][pos] = src;
        }
    }
}

// ------------------------- per-node attention logits -------------------------
__global__ void k_alpha(const float* __restrict__ as0, const float* __restrict__ ad0,
                        const float* __restrict__ as1, const float* __restrict__ ad1) {
    __shared__ float a[4][128];
    int tid = threadIdx.x;
    if (tid < 128) {
        a[0][tid] = as0[tid];
        a[1][tid] = ad0[tid];
        a[2][tid] = as1[tid];
        a[3][tid] = ad1[tid];
    }
    __syncthreads();
    int n = blockIdx.x * blockDim.x + tid;
    if (n >= NN) return;
    float r[4][8];
#pragma unroll
    for (int t = 0; t < 4; t++)
#pragma unroll
        for (int h = 0; h < 8; h++) r[t][h] = 0.f;
    const float4* xp4 = (const float4*)&g_xp[(size_t)n * 128];
#pragma unroll
    for (int j4 = 0; j4 < 32; j4++) {
        float4 v = xp4[j4];
        int j = j4 * 4;
        int h = j >> 4;
        float c[4] = {v.x, v.y, v.z, v.w};
#pragma unroll
        for (int cc = 0; cc < 4; cc++)
#pragma unroll
            for (int t = 0; t < 4; t++) r[t][h] = fmaf(c[cc], a[t][j + cc], r[t][h]);
    }
    *(float4*)&g_as[0][n * 8]     = make_float4(r[0][0], r[0][1], r[0][2], r[0][3]);
    *(float4*)&g_as[0][n * 8 + 4] = make_float4(r[0][4], r[0][5], r[0][6], r[0][7]);
    *(float4*)&g_ad[0][n * 8]     = make_float4(r[1][0], r[1][1], r[1][2], r[1][3]);
    *(float4*)&g_ad[0][n * 8 + 4] = make_float4(r[1][4], r[1][5], r[1][6], r[1][7]);
    *(float4*)&g_as[1][n * 8]     = make_float4(r[2][0], r[2][1], r[2][2], r[2][3]);
    *(float4*)&g_as[1][n * 8 + 4] = make_float4(r[2][4], r[2][5], r[2][6], r[2][7]);
    *(float4*)&g_ad[1][n * 8]     = make_float4(r[3][0], r[3][1], r[3][2], r[3][3]);
    *(float4*)&g_ad[1][n * 8 + 4] = make_float4(r[3][4], r[3][5], r[3][6], r[3][7]);
}

// --------- fused edge kernel: exp+denom (smem-staged) then fp16 aggregate (4-wide MLP) ---------
__device__ __forceinline__ float4 ld_xp16(int s, int lane) {
    uint2 u = *(const uint2*)&g_xp16[(size_t)s * 128 + lane * 4];
    float2 f0 = __half22float2(*reinterpret_cast<__half2*>(&u.x));
    float2 f1 = __half22float2(*reinterpret_cast<__half2*>(&u.y));
    return make_float4(f0.x, f0.y, f1.x, f1.y);
}

__global__ void __launch_bounds__(256) k_edge() {
    __shared__ float exbuf[8][EDGE_CAP * 8];   // 16KB
    int m = blockIdx.y;
    int w = (blockIdx.x * blockDim.x + threadIdx.x) >> 5;
    int wl = threadIdx.x >> 5;
    int lane = threadIdx.x & 31;
    if (w >= NN) return;
    int beg = g_off[m][w], end = g_off[m][w + 1];
    int deg = end - beg;
    bool fits = (deg <= EDGE_CAP);

    float4 ad0 = *(const float4*)&g_ad[m][w * 8];
    float4 ad1 = *(const float4*)&g_ad[m][w * 8 + 4];
    float den[8];
#pragma unroll
    for (int h = 0; h < 8; h++) den[h] = 0.f;
    for (int e = beg + lane; e < end; e += 32) {
        int src = g_srcs[m][e];
        float4 s0 = *(const float4*)&g_as[m][src * 8];
        float4 s1 = *(const float4*)&g_as[m][src * 8 + 4];
        float t[8] = {s0.x + ad0.x, s0.y + ad0.y, s0.z + ad0.z, s0.w + ad0.w,
                      s1.x + ad1.x, s1.y + ad1.y, s1.z + ad1.z, s1.w + ad1.w};
        float ex[8];
#pragma unroll
        for (int h = 0; h < 8; h++) {
            float l = t[h] > 0.f ? t[h] : 0.2f * t[h];
            ex[h] = fexp(l);
            den[h] += ex[h];
        }
        if (fits) {
            float* dst = &exbuf[wl][(e - beg) * 8];
            *(float4*)dst       = make_float4(ex[0], ex[1], ex[2], ex[3]);
            *(float4*)(dst + 4) = make_float4(ex[4], ex[5], ex[6], ex[7]);
        } else {
            *(float4*)&g_e[m][(size_t)e * 8]     = make_float4(ex[0], ex[1], ex[2], ex[3]);
            *(float4*)&g_e[m][(size_t)e * 8 + 4] = make_float4(ex[4], ex[5], ex[6], ex[7]);
        }
    }
#pragma unroll
    for (int h = 0; h < 8; h++)
#pragma unroll
        for (int o = 16; o > 0; o >>= 1) den[h] += __shfl_xor_sync(0xffffffffu, den[h], o);
    __syncwarp();

    int h = lane >> 2;
    float iv = __fdividef(1.f, den[h] + 1e-16f);
    float4 acc = make_float4(0.f, 0.f, 0.f, 0.f);
    const int* sb = g_srcs[m];
    if (fits) {
        const float* xb = exbuf[wl];
        int j = 0;
        for (; j + 4 <= deg; j += 4) {
            int e = beg + j;
            int s0 = sb[e], s1 = sb[e + 1], s2 = sb[e + 2], s3 = sb[e + 3];
            float x0 = xb[j * 8 + h];
            float x1 = xb[(j + 1) * 8 + h];
            float x2 = xb[(j + 2) * 8 + h];
            float x3 = xb[(j + 3) * 8 + h];
            float4 v0 = ld_xp16(s0, lane);
            float4 v1 = ld_xp16(s1, lane);
            float4 v2 = ld_xp16(s2, lane);
            float4 v3 = ld_xp16(s3, lane);
            acc.x = fmaf(v0.x, x0, acc.x); acc.y = fmaf(v0.y, x0, acc.y);
            acc.z = fmaf(v0.z, x0, acc.z); acc.w = fmaf(v0.w, x0, acc.w);
            acc.x = fmaf(v1.x, x1, acc.x); acc.y = fmaf(v1.y, x1, acc.y);
            acc.z = fmaf(v1.z, x1, acc.z); acc.w = fmaf(v1.w, x1, acc.w);
            acc.x = fmaf(v2.x, x2, acc.x); acc.y = fmaf(v2.y, x2, acc.y);
            acc.z = fmaf(v2.z, x2, acc.z); acc.w = fmaf(v2.w, x2, acc.w);
            acc.x = fmaf(v3.x, x3, acc.x); acc.y = fmaf(v3.y, x3, acc.y);
            acc.w = fmaf(v3.w, x3, acc.w); acc.z = fmaf(v3.z, x3, acc.z);
        }
        for (; j < deg; j++) {
            int s0 = sb[beg + j];
            float x0 = xb[j * 8 + h];
            float4 v0 = ld_xp16(s0, lane);
            acc.x = fmaf(v0.x, x0, acc.x); acc.y = fmaf(v0.y, x0, acc.y);
            acc.z = fmaf(v0.z, x0, acc.z); acc.w = fmaf(v0.w, x0, acc.w);
        }
    } else {
        const float* eb = g_e[m];
        for (int e = beg; e < end; e++) {
            int s0 = sb[e];
            float x0 = eb[(size_t)e * 8 + h];
            float4 v0 = ld_xp16(s0, lane);
            acc.x = fmaf(v0.x, x0, acc.x); acc.y = fmaf(v0.y, x0, acc.y);
            acc.z = fmaf(v0.z, x0, acc.z); acc.w = fmaf(v0.w, x0, acc.w);
        }
    }
    float2 o01 = make_float2(fmaxf(acc.x * iv, 0.f), fmaxf(acc.y * iv, 0.f));
    float2 o23 = make_float2(fmaxf(acc.z * iv, 0.f), fmaxf(acc.w * iv, 0.f));
    uint2 st;
    *reinterpret_cast<__half2*>(&st.x) = __floats2half2_rn(o01.x, o01.y);
    *reinterpret_cast<__half2*>(&st.y) = __floats2half2_rn(o23.x, o23.y);
    *(uint2*)&g_acc16[m][(size_t)w * 128 + lane * 4] = st;
}

// ------------------------- semantic GEMM wrapper -------------------------
__global__ void __launch_bounds__(256) k_sem(const float* __restrict__ kw,
                                             const float* __restrict__ kb) {
    extern __shared__ char smem[];
    int m = blockIdx.y;
    gemm_body<128, 1>(blockIdx.x, m, (const float*)0, g_acc16[m], kw, kb, smem);
}

// ------------------------- semantic softmax -------------------------
__global__ void k_attn(const float* __restrict__ q) {
    int j = threadIdx.x;
    __shared__ float red[8];
    float qv = q[j];
    float s0 = g_ksum[j] * qv;
    float s1 = g_ksum[128 + j] * qv;
#pragma unroll
    for (int o = 16; o > 0; o >>= 1) {
        s0 += __shfl_xor_sync(0xffffffffu, s0, o);
        s1 += __shfl_xor_sync(0xffffffffu, s1, o);
    }
    int lane = j & 31, wid = j >> 5;
    if (lane == 0) {
        red[wid] = s0;
        red[4 + wid] = s1;
    }
    __syncthreads();
    if (j == 0) {
        float t0 = (red[0] + red[1] + red[2] + red[3]) / (float)NN;
        float t1 = (red[4] + red[5] + red[6] + red[7]) / (float)NN;
        float mx = fmaxf(t0, t1);
        float e0 = fexp(t0 - mx), e1 = fexp(t1 - mx);
        float inv = __fdividef(1.f, e0 + e1);
        g_attn[0] = e0 * inv;
        g_attn[1] = e1 * inv;
    }
}

// ------------------------- fused output linear (fp16 g_acc16 inputs) -------------------------
__global__ void k_final(const float* __restrict__ lw, const float* __restrict__ lb,
                        float* __restrict__ out) {
    __shared__ float ws[512];
    __shared__ float bs[4];
    int tid = threadIdx.x;
    ws[tid] = lw[tid];
    ws[tid + 256] = lw[tid + 256];
    if (tid < 4) bs[tid] = lb[tid];
    __syncthreads();
    int n = blockIdx.x * blockDim.x + tid;
    if (n >= NN) return;
    float a0 = g_attn[0], a1 = g_attn[1];
    float o0 = bs[0], o1 = bs[1], o2 = bs[2], o3 = bs[3];
    const uint2* p0 = (const uint2*)&g_acc16[0][(size_t)n * 128];
    const uint2* p1 = (const uint2*)&g_acc16[1][(size_t)n * 128];
#pragma unroll 8
    for (int j4 = 0; j4 < 32; j4++) {
        uint2 u0 = p0[j4];
        uint2 u1 = p1[j4];
        float2 a00 = __half22float2(*reinterpret_cast<__half2*>(&u0.x));
        float2 a01 = __half22float2(*reinterpret_cast<__half2*>(&u0.y));
        float2 a10 = __half22float2(*reinterpret_cast<__half2*>(&u1.x));
        float2 a11 = __half22float2(*reinterpret_cast<__half2*>(&u1.y));
        float c0[4] = {a00.x, a00.y, a01.x, a01.y};
        float c1[4] = {a10.x, a10.y, a11.x, a11.y};
#pragma unroll
        for (int jj = 0; jj < 4; jj++) {
            float f = fmaf(a0, c0[jj], a1 * c1[jj]);
            int j = j4 * 4 + jj;
            o0 = fmaf(f, ws[j * 4 + 0], o0);
            o1 = fmaf(f, ws[j * 4 + 1], o1);
            o2 = fmaf(f, ws[j * 4 + 2], o2);
            o3 = fmaf(f, ws[j * 4 + 3], o3);
        }
    }
    *(float4*)(out + (size_t)n * 4) = make_float4(o0, o1, o2, o3);
}

// ------------------------- launch -------------------------
extern "C" void kernel_launch(void* const* d_in, const int* in_sizes, int n_in,
                              void* d_out, int out_size) {
    const float* x   = (const float*)d_in[0];
    const void*  e0  = d_in[1];
    const void*  e1  = d_in[2];
    const float* pw  = (const float*)d_in[3];
    const float* pb  = (const float*)d_in[4];
    const float* as0 = (const float*)d_in[5];
    const float* ad0 = (const float*)d_in[6];
    const float* as1 = (const float*)d_in[7];
    const float* ad1 = (const float*)d_in[8];
    const float* kw  = (const float*)d_in[9];
    const float* kb  = (const float*)d_in[10];
    const float* q   = (const float*)d_in[11];
    const float* lw  = (const float*)d_in[12];
    const float* lb  = (const float*)d_in[13];
    float* out = (float*)d_out;

    cudaFuncSetAttribute(k_proj, cudaFuncAttributeMaxDynamicSharedMemorySize, SM_TOT);
    cudaFuncSetAttribute(k_sem, cudaFuncAttributeMaxDynamicSharedMemorySize, SM_TOT);

    bool fork = g_sok;
    if (fork) {
        // fork: proj + alpha concurrently with the CSR build chain
        cudaEventRecord(g_evf, 0);
        cudaStreamWaitEvent(g_side, g_evf, 0);
        k_proj<<<GB, 256, SM_TOT, g_side>>>(x, pw, pb);
        k_alpha<<<(NN + 255) / 256, 256, 0, g_side>>>(as0, ad0, as1, ad1);
        cudaEventRecord(g_evj, g_side);
    }

    k_init<<<1 + (2 * NN + 255) / 256, 256>>>(e0);
    k_hist<<<(2 * NE + 255) / 256, 256>>>(e0, e1);
    dim3 gsA(NB, 2);
    k_scanA<<<gsA, SCAN_B>>>();
    k_scanB<<<2, 128>>>();
    dim3 gsC((NN + 255) / 256, 2);
    k_scanC<<<gsC, 256>>>();
    k_scatter<<<NSCAT, 256>>>(e0, e1);

    if (fork) {
        cudaStreamWaitEvent(0, g_evj, 0);   // join: g_xp/g_xp16/g_as/g_ad ready
    } else {
        k_proj<<<GB, 256, SM_TOT>>>(x, pw, pb);
        k_alpha<<<(NN + 255) / 256, 256>>>(as0, ad0, as1, ad1);
    }
    dim3 ge((NN * 32 + 255) / 256, 2);
    k_edge<<<ge, 256>>>();
    dim3 gg(GB, 2);
    k_sem<<<gg, 256, SM_TOT>>>(kw, kb);
    k_attn<<<1, 128>>>(q);
    k_final<<<(NN + 255) / 256, 256>>>(lw, lb, out);
}